// round 15
// baseline (speedup 1.0000x reference)
#include <cuda_runtime.h>
#include <cuda_fp16.h>
#include <stdint.h>
#include <math.h>

// Problem constants
#define SEQ 2048
#define BB  4
#define DD  1024
#define HH  16
#define DH  64
#define MM  (SEQ*BB)

// ---------------- scratch (device globals; allocation-free) ----------------
__device__ __half g_xh[MM*DD];
__device__ __half g_wqh[DD*DD], g_wkh[DD*DD], g_wvh[DD*DD], g_woh[DD*DD];
__device__ __half g_qh[MM*DD];   // scaled x16 incl beta, [b,h,s,dh]
__device__ __half g_kh[MM*DD];   // [b,h,s,dh]
__device__ __half g_vh[MM*DD];   // transposed [b,h,dh,s]
__device__ __half g_ah[MM*DD];   // att output [s,b,D]

// ---------------- PTX helpers (baseline ISA only) ----------------
static __device__ __forceinline__ uint32_t s2u(const void* p) {
    return (uint32_t)__cvta_generic_to_shared(p);
}

#define CP_ASYNC16(saddr, gptr) \
    asm volatile("cp.async.cg.shared.global [%0], [%1], 16;" :: "r"(saddr), "l"(gptr))
#define CP_COMMIT() asm volatile("cp.async.commit_group;" ::: "memory")
#define CP_WAIT(n)  asm volatile("cp.async.wait_group %0;" :: "n"(n) : "memory")

static __device__ __forceinline__ void ldsm_x4(uint32_t addr,
    uint32_t &r0, uint32_t &r1, uint32_t &r2, uint32_t &r3)
{
    asm volatile("ldmatrix.sync.aligned.m8n8.x4.shared.b16 {%0,%1,%2,%3}, [%4];"
        : "=r"(r0), "=r"(r1), "=r"(r2), "=r"(r3) : "r"(addr));
}

static __device__ __forceinline__ void mma16816(float* d,
    uint32_t a0, uint32_t a1, uint32_t a2, uint32_t a3, uint32_t b0, uint32_t b1)
{
    asm volatile("mma.sync.aligned.m16n8k16.row.col.f32.f16.f16.f32 "
        "{%0,%1,%2,%3}, {%4,%5,%6,%7}, {%8,%9}, {%0,%1,%2,%3};"
        : "+f"(d[0]), "+f"(d[1]), "+f"(d[2]), "+f"(d[3])
        : "r"(a0), "r"(a1), "r"(a2), "r"(a3), "r"(b0), "r"(b1));
}

static __device__ __forceinline__ uint32_t packh(float x, float y) {
    __half2 t = __floats2half2_rn(x, y);
    return *(uint32_t*)&t;
}

// ---------------- conversion kernels ----------------
__global__ void convx_kernel(const float* __restrict__ src,
                             __half* __restrict__ hi, int n4)
{
    int i = blockIdx.x * blockDim.x + threadIdx.x;
    if (i >= n4) return;
    float4 v = ((const float4*)src)[i];
    uint2 o;
    o.x = packh(v.x, v.y);
    o.y = packh(v.z, v.w);
    ((uint2*)hi)[i] = o;
}

__global__ void split4_kernel(const float* __restrict__ s0, const float* __restrict__ s1,
                              const float* __restrict__ s2, const float* __restrict__ s3,
                              int n4)
{
    int i = blockIdx.x * blockDim.x + threadIdx.x;
    if (i >= n4) return;
    const float* src; __half* hi;
    switch (blockIdx.y) {
        case 0:  src = s0; hi = g_wqh; break;
        case 1:  src = s1; hi = g_wkh; break;
        case 2:  src = s2; hi = g_wvh; break;
        default: src = s3; hi = g_woh; break;
    }
    float4 v = ((const float4*)src)[i];
    uint2 oh;
    oh.x = packh(v.x * 64.0f, v.y * 64.0f);
    oh.y = packh(v.z * 64.0f, v.w * 64.0f);
    ((uint2*)hi)[i] = oh;
}

// ---------------------------------------------------------------------------
// HMMA GEMM body (1-pass fp16): unchanged from R13/R14 passing config.
// ---------------------------------------------------------------------------
#define GBK 64
#define NCG (DD / GBK)            // 16
#define RSMEM 144
#define A_T (128 * RSMEM)         // 18432
#define B_T (64 * RSMEM)          // 9216
#define BUF_B (A_T + B_T)         // 27648
#define GEMM_SMEM (2 * BUF_B)     // 55296

static __device__ __forceinline__ void gemm_load_chunk(
    const __half* __restrict__ A, const __half* __restrict__ Bhi,
    int bm, int bn, int k0, uint32_t sa_base, int tid)
{
    const __half* ga = A   + (size_t)bm * DD + k0;
    const __half* gb = Bhi + (size_t)bn * DD + k0;
    #pragma unroll
    for (int u = 0; u < 4; u++) {
        int idx = tid + u * 256;
        int row = idx >> 3, seg = idx & 7;
        CP_ASYNC16(sa_base + row * RSMEM + seg * 16,
                   ga + (size_t)row * DD + seg * 8);
    }
    #pragma unroll
    for (int u = 0; u < 2; u++) {
        int idx = tid + u * 256;
        int row = idx >> 3, seg = idx & 7;
        CP_ASYNC16(sa_base + A_T + row * RSMEM + seg * 16,
                   gb + (size_t)row * DD + seg * 8);
    }
}

static __device__ __forceinline__ void gemm_body(
    const __half* __restrict__ A, const __half* __restrict__ Bhi,
    const float* __restrict__ bias, int mode,
    const float* __restrict__ beta,
    float* __restrict__ C, __half* __restrict__ Oh,
    int bn, int bm, char* smc)
{
    const int tid  = threadIdx.x;
    const int wid  = tid >> 5;
    const int lane = tid & 31;
    const uint32_t sb = s2u(smc);

    const int m0 = (wid >> 1) * 32;
    const int n0 = (wid & 1) * 32;

    gemm_load_chunk(A, Bhi, bm, bn, 0, sb, tid);
    CP_COMMIT();

    float acc[2][4][4];
    #pragma unroll
    for (int mi = 0; mi < 2; mi++)
        #pragma unroll
        for (int ni = 0; ni < 4; ni++)
            #pragma unroll
            for (int f = 0; f < 4; f++) acc[mi][ni][f] = 0.0f;

    for (int c = 0; c < NCG; c++) {
        if (c + 1 < NCG) {
            gemm_load_chunk(A, Bhi, bm, bn, (c + 1) * GBK,
                            sb + ((c + 1) & 1) * BUF_B, tid);
            CP_COMMIT();
            CP_WAIT(1);
        } else {
            CP_WAIT(0);
        }
        __syncthreads();

        const uint32_t bufo = (c & 1) * BUF_B;
        const uint32_t AT  = sb + bufo;
        const uint32_t BhT = AT + A_T;

        #pragma unroll
        for (int s = 0; s < 4; s++) {
            const uint32_t kb = s * 32;
            uint32_t bh[4][2], ah[2][4];
            {
                int g = lane >> 3;
                int ntl = g >> 1, half = g & 1;
                uint32_t boff = (uint32_t)(n0 + ntl * 8 + (lane & 7)) * RSMEM
                              + kb + half * 16;
                ldsm_x4(BhT + boff,              bh[0][0], bh[0][1], bh[1][0], bh[1][1]);
                ldsm_x4(BhT + boff + 16 * RSMEM, bh[2][0], bh[2][1], bh[3][0], bh[3][1]);
            }
            #pragma unroll
            for (int mi = 0; mi < 2; mi++) {
                uint32_t aoff = (uint32_t)(m0 + mi * 16 + (lane & 15)) * RSMEM
                              + kb + (lane >> 4) * 16;
                ldsm_x4(AT + aoff, ah[mi][0], ah[mi][1], ah[mi][2], ah[mi][3]);
            }
            #pragma unroll
            for (int mi = 0; mi < 2; mi++)
                #pragma unroll
                for (int ni = 0; ni < 4; ni++)
                    mma16816(acc[mi][ni], ah[mi][0], ah[mi][1], ah[mi][2], ah[mi][3],
                             bh[ni][0], bh[ni][1]);
        }
        __syncthreads();
    }

    const float DS = 1.0f / 64.0f;
    const int erow = lane >> 2;
    const int ecol = (lane & 3) * 2;
    #pragma unroll
    for (int mi = 0; mi < 2; mi++) {
        #pragma unroll
        for (int ni = 0; ni < 4; ni++) {
            int gr = bm + m0 + mi * 16 + erow;
            int gc = bn + n0 + ni * 8 + ecol;
            float v0x = acc[mi][ni][0] * DS + bias[gc];
            float v0y = acc[mi][ni][1] * DS + bias[gc + 1];
            float v1x = acc[mi][ni][2] * DS + bias[gc];
            float v1y = acc[mi][ni][3] * DS + bias[gc + 1];
            if (mode == 0) {
                float2 a = {v0x, v0y}, bb2 = {v1x, v1y};
                *(float2*)(C + (size_t)gr * DD + gc)       = a;
                *(float2*)(C + (size_t)(gr + 8) * DD + gc) = bb2;
            } else {
                int hh = gc >> 6, dh = gc & 63;
                int s0 = gr >> 2, bbi = gr & 3;
                if (mode == 1 || mode == 3) {
                    if (mode == 1) {
                        float f = 2.0f * __expf(-beta[hh]);
                        v0x *= f; v0y *= f; v1x *= f; v1y *= f;
                    }
                    size_t off0 = (((size_t)bbi * HH + hh) * SEQ + s0) * DH + dh;
                    size_t off1 = off0 + 2 * DH;
                    *(uint32_t*)(Oh + off0) = packh(v0x, v0y);
                    *(uint32_t*)(Oh + off1) = packh(v1x, v1y);
                } else {
                    size_t off = (((size_t)bbi * HH + hh) * DH + dh) * SEQ + s0;
                    Oh[off]           = __float2half_rn(v0x);
                    Oh[off + SEQ]     = __float2half_rn(v0y);
                    Oh[off + 2]       = __float2half_rn(v1x);
                    Oh[off + SEQ + 2] = __float2half_rn(v1y);
                }
            }
        }
    }
}

__global__ __launch_bounds__(256, 3)
void gemm_qkv_kernel(const float* __restrict__ beta,
                     const float* __restrict__ bq,
                     const float* __restrict__ bk,
                     const float* __restrict__ bv)
{
    extern __shared__ char smc[];
    const int bn = blockIdx.x * 64;
    const int bm = blockIdx.y * 128;
    if (blockIdx.z == 0)
        gemm_body(g_xh, g_wqh, bq, 1, beta, nullptr, g_qh, bn, bm, smc);
    else if (blockIdx.z == 1)
        gemm_body(g_xh, g_wkh, bk, 3, nullptr, nullptr, g_kh, bn, bm, smc);
    else
        gemm_body(g_xh, g_wvh, bv, 2, nullptr, nullptr, g_vh, bn, bm, smc);
}

__global__ __launch_bounds__(256, 3)
void gemm_out_kernel(const float* __restrict__ bo, float* __restrict__ out)
{
    extern __shared__ char smc[];
    const int bn = blockIdx.x * 64;
    const int bm = blockIdx.y * 128;
    gemm_body(g_ah, g_woh, bo, 0, nullptr, out, nullptr, bn, bm, smc);
}

// ---------------------------------------------------------------------------
// Flash attention, 128-row Q tiles, 256 thr / 8 warps (16 rows per warp).
// Sink-anchored max-free softmax: p_scaled = exp2(S*C2F + BFOLD).
// K/V tile loads per (b,h) drop from 528 to 272 vs the 64-row version.
// smem: Q 128xFRB + 2 stages x (K 64xFRB + V 64xFRB) = 55296 -> 3 CTAs/SM.
// ---------------------------------------------------------------------------
#define FRB 144
#define QT_B (128 * FRB)           // 18432
#define KT_B (64 * FRB)            // 9216
#define STG_B (2 * KT_B)           // 18432
#define FLASH_SMEM (QT_B + 2 * STG_B)   // 55296
#define C2F   0.0901684400556f     // 0.0625 * log2(e)
#define BFOLD (-6.4269504089f)     // 8 - 10*log2(e)
#define LSINK 0.0116223822f        // 256*exp(-10)

static __device__ __forceinline__ void ldsm_b(uint32_t tile, int nbase, int ksb,
                                              int lane, uint32_t* r4)
{
    int g = lane >> 3, ntl = g >> 1, half = g & 1;
    uint32_t addr = tile + (uint32_t)(nbase + ntl * 8 + (lane & 7)) * FRB
                  + ksb + half * 16;
    ldsm_x4(addr, r4[0], r4[1], r4[2], r4[3]);
}

__global__ __launch_bounds__(256, 3)
void flash_mma_kernel(const __half* __restrict__ qh_g,
                      const __half* __restrict__ kh_g,
                      const __half* __restrict__ vh_g,
                      __half* __restrict__ ah_g)
{
    extern __shared__ char smf[];
    const int tid = threadIdx.x, lane = tid & 31, wid = tid >> 5;
    const int qb = (int)gridDim.x - 1 - (int)blockIdx.x;   // LPT order
    const int h = blockIdx.y, b = blockIdx.z;
    const int q0 = qb * 128;
    const int njt = 2 * qb + 2;      // number of 64-key tiles
    const uint32_t sb = s2u(smf);
    const uint32_t qhS = sb;

    const size_t bh = (size_t)b * HH + h;
    const char* qhp = (const char*)(qh_g + (bh * SEQ + q0) * DH);
    const __half* khp = kh_g + bh * SEQ * DH;
    const __half* vhp = vh_g + bh * (size_t)DH * SEQ;

    // Q tile: 128 rows x 128 B = 1024 segs / 256 thr = 4 each
    #pragma unroll
    for (int u = 0; u < 4; u++) {
        int idx = tid + u * 256; int row = idx >> 3, seg = idx & 7;
        CP_ASYNC16(qhS + row * FRB + seg * 16, qhp + row * 128 + seg * 16);
    }
    CP_COMMIT();

    // stage 0 prefetch: K 512 segs + V 512 segs = 4 per thread
    {
        uint32_t base = sb + QT_B;
        #pragma unroll
        for (int u = 0; u < 2; u++) {
            int idx = tid + u * 256; int row = idx >> 3, seg = idx & 7;
            CP_ASYNC16(base + row * FRB + seg * 16, khp + (size_t)row * DH + seg * 8);
            CP_ASYNC16(base + KT_B + row * FRB + seg * 16, vhp + (size_t)row * SEQ + seg * 8);
        }
        CP_COMMIT();
    }
    CP_WAIT(0);
    __syncthreads();

    const int qrow0 = wid * 16;      // 0..112
    uint32_t qah[4][4];
    #pragma unroll
    for (int ks = 0; ks < 4; ks++) {
        uint32_t ah = qhS + (uint32_t)(qrow0 + (lane & 15)) * FRB + ks * 32 + (lane >> 4) * 16;
        ldsm_x4(ah, qah[ks][0], qah[ks][1], qah[ks][2], qah[ks][3]);
    }

    float Oa[8][4];
    #pragma unroll
    for (int nt = 0; nt < 8; nt++)
        #pragma unroll
        for (int f = 0; f < 4; f++) Oa[nt][f] = 0.0f;
    float lrow[2] = {LSINK, LSINK};

    for (int jt = 0; jt < njt; jt++) {
        const int s = jt & 1;
        if (jt + 1 < njt) {
            uint32_t base = sb + QT_B + (s ^ 1) * STG_B;
            const int j1 = (jt + 1) * 64;
            #pragma unroll
            for (int u = 0; u < 2; u++) {
                int idx = tid + u * 256; int row = idx >> 3, seg = idx & 7;
                CP_ASYNC16(base + row * FRB + seg * 16,
                           khp + (size_t)(j1 + row) * DH + seg * 8);
                CP_ASYNC16(base + KT_B + row * FRB + seg * 16,
                           vhp + (size_t)row * SEQ + j1 + seg * 8);
            }
            CP_COMMIT();
            CP_WAIT(1);
        } else {
            CP_WAIT(0);
        }
        __syncthreads();

        const uint32_t st = sb + QT_B + s * STG_B;
        const uint32_t khT = st, vhT = st + KT_B;

        // ---- S = Qh Kh^T (raw x16 units) ----
        float S[8][4];
        #pragma unroll
        for (int nt = 0; nt < 8; nt++)
            #pragma unroll
            for (int f = 0; f < 4; f++) S[nt][f] = 0.0f;

        #pragma unroll
        for (int ks = 0; ks < 4; ks++) {
            uint32_t kh4[16];
            #pragma unroll
            for (int p = 0; p < 4; p++)
                ldsm_b(khT, p * 16, ks * 32, lane, kh4 + p * 4);
            #pragma unroll
            for (int nt = 0; nt < 8; nt++)
                mma16816(S[nt], qah[ks][0], qah[ks][1], qah[ks][2], qah[ks][3],
                         kh4[2 * nt], kh4[2 * nt + 1]);
        }

        // causal mask: only tiles overlapping this warp's row range
        if (jt * 64 + 63 > q0 + qrow0) {
            const int j0 = jt * 64;
            #pragma unroll
            for (int nt = 0; nt < 8; nt++) {
                #pragma unroll
                for (int e = 0; e < 4; e++) {
                    int grow = q0 + qrow0 + (lane >> 2) + ((e >= 2) ? 8 : 0);
                    int gcol = j0 + nt * 8 + (lane & 3) * 2 + (e & 1);
                    if (gcol > grow) S[nt][e] = -1e30f;
                }
            }
        }

        // ---- max-free softmax: p_scaled = exp2(S*C2F + BFOLD) ----
        #pragma unroll
        for (int i = 0; i < 2; i++) {
            float rs = 0.0f;
            #pragma unroll
            for (int nt = 0; nt < 8; nt++) {
                float p0 = exp2f(fmaf(S[nt][2 * i],     C2F, BFOLD));
                float p1 = exp2f(fmaf(S[nt][2 * i + 1], C2F, BFOLD));
                S[nt][2 * i] = p0; S[nt][2 * i + 1] = p1;
                rs += p0 + p1;
            }
            rs += __shfl_xor_sync(0xffffffffu, rs, 1);
            rs += __shfl_xor_sync(0xffffffffu, rs, 2);
            lrow[i] += rs;
        }

        // ---- O += P_scaled Vh ----
        #pragma unroll
        for (int ks = 0; ks < 4; ks++) {
            uint32_t ah0 = packh(S[2 * ks][0],     S[2 * ks][1]);
            uint32_t ah1 = packh(S[2 * ks][2],     S[2 * ks][3]);
            uint32_t ah2 = packh(S[2 * ks + 1][0], S[2 * ks + 1][1]);
            uint32_t ah3 = packh(S[2 * ks + 1][2], S[2 * ks + 1][3]);
            uint32_t vh4[16];
            #pragma unroll
            for (int p = 0; p < 4; p++)
                ldsm_b(vhT, p * 16, ks * 32, lane, vh4 + p * 4);
            #pragma unroll
            for (int nt = 0; nt < 8; nt++)
                mma16816(Oa[nt], ah0, ah1, ah2, ah3, vh4[2 * nt], vh4[2 * nt + 1]);
        }
        __syncthreads();
    }

    // ---- epilogue: O = Oa / lrow, store fp16 [s,b,D] ----
    const float inv0 = 1.0f / lrow[0];
    const float inv1 = 1.0f / lrow[1];
    const int r = lane >> 2, c2 = (lane & 3) * 2;
    const int srow0 = q0 + qrow0 + r;
    #pragma unroll
    for (int nt = 0; nt < 8; nt++) {
        int col = h * 64 + nt * 8 + c2;
        float o00 = Oa[nt][0] * inv0, o01 = Oa[nt][1] * inv0;
        float o10 = Oa[nt][2] * inv1, o11 = Oa[nt][3] * inv1;
        size_t off0 = ((size_t)srow0 * BB + b) * DD + col;
        size_t off1 = ((size_t)(srow0 + 8) * BB + b) * DD + col;
        *(uint32_t*)(ah_g + off0) = packh(o00, o01);
        *(uint32_t*)(ah_g + off1) = packh(o10, o11);
    }
}

// ---------------------------------------------------------------------------
extern "C" void kernel_launch(void* const* d_in, const int* in_sizes, int n_in,
                              void* d_out, int out_size)
{
    const float* x    = (const float*)d_in[0];
    const float* beta = (const float*)d_in[2];
    const float* Wq   = (const float*)d_in[3];
    const float* bq   = (const float*)d_in[4];
    const float* Wk   = (const float*)d_in[5];
    const float* bk   = (const float*)d_in[6];
    const float* Wv   = (const float*)d_in[7];
    const float* bv   = (const float*)d_in[8];
    const float* Wo   = (const float*)d_in[9];
    const float* bo   = (const float*)d_in[10];
    float* out = (float*)d_out;

    __half *xh, *qh, *kh, *vh, *ah;
    cudaGetSymbolAddress((void**)&xh, g_xh);
    cudaGetSymbolAddress((void**)&qh, g_qh);
    cudaGetSymbolAddress((void**)&kh, g_kh);
    cudaGetSymbolAddress((void**)&vh, g_vh);
    cudaGetSymbolAddress((void**)&ah, g_ah);

    cudaFuncSetAttribute(gemm_qkv_kernel,
                         cudaFuncAttributeMaxDynamicSharedMemorySize, GEMM_SMEM);
    cudaFuncSetAttribute(gemm_out_kernel,
                         cudaFuncAttributeMaxDynamicSharedMemorySize, GEMM_SMEM);
    cudaFuncSetAttribute(flash_mma_kernel,
                         cudaFuncAttributeMaxDynamicSharedMemorySize, FLASH_SMEM);

    const int nx4 = MM * DD / 4;
    const int nw4 = DD * DD / 4;

    convx_kernel<<<(nx4 + 255) / 256, 256>>>(x, xh, nx4);
    {
        dim3 sg((nw4 + 255) / 256, 4);
        split4_kernel<<<sg, 256>>>(Wq, Wk, Wv, Wo, nw4);
    }

    dim3 qkvgrid(DD / 64, MM / 128, 3);   // (16, 64, 3)
    gemm_qkv_kernel<<<qkvgrid, 256, GEMM_SMEM>>>(beta, bq, bk, bv);

    dim3 fgrid(SEQ / 128, HH, BB);   // (16, 16, 4)
    flash_mma_kernel<<<fgrid, 256, FLASH_SMEM>>>(qh, kh, vh, ah);

    dim3 ogrid(DD / 64, MM / 128);   // (16, 64)
    gemm_out_kernel<<<ogrid, 256, GEMM_SMEM>>>(bo, out);
}

// round 16
// speedup vs baseline: 1.1699x; 1.1699x over previous
#include <cuda_runtime.h>
#include <cuda_fp16.h>
#include <stdint.h>
#include <math.h>

// Problem constants
#define SEQ 2048
#define BB  4
#define DD  1024
#define HH  16
#define DH  64
#define MM  (SEQ*BB)

// ---------------- scratch (device globals; allocation-free) ----------------
__device__ __half g_xh[MM*DD];
__device__ __half g_wqh[DD*DD], g_wkh[DD*DD], g_wvh[DD*DD], g_woh[DD*DD];
__device__ __half g_qh[MM*DD];   // scaled x16 incl beta, [b,h,s,dh]
__device__ __half g_kh[MM*DD];   // [b,h,s,dh]
__device__ __half g_vh[MM*DD];   // transposed [b,h,dh,s]
__device__ __half g_ah[MM*DD];   // att output [s,b,D]

// ---------------- PTX helpers (baseline ISA only) ----------------
static __device__ __forceinline__ uint32_t s2u(const void* p) {
    return (uint32_t)__cvta_generic_to_shared(p);
}

#define CP_ASYNC16(saddr, gptr) \
    asm volatile("cp.async.cg.shared.global [%0], [%1], 16;" :: "r"(saddr), "l"(gptr))
#define CP_COMMIT() asm volatile("cp.async.commit_group;" ::: "memory")
#define CP_WAIT(n)  asm volatile("cp.async.wait_group %0;" :: "n"(n) : "memory")

static __device__ __forceinline__ void ldsm_x4(uint32_t addr,
    uint32_t &r0, uint32_t &r1, uint32_t &r2, uint32_t &r3)
{
    asm volatile("ldmatrix.sync.aligned.m8n8.x4.shared.b16 {%0,%1,%2,%3}, [%4];"
        : "=r"(r0), "=r"(r1), "=r"(r2), "=r"(r3) : "r"(addr));
}

static __device__ __forceinline__ void mma16816(float* d,
    uint32_t a0, uint32_t a1, uint32_t a2, uint32_t a3, uint32_t b0, uint32_t b1)
{
    asm volatile("mma.sync.aligned.m16n8k16.row.col.f32.f16.f16.f32 "
        "{%0,%1,%2,%3}, {%4,%5,%6,%7}, {%8,%9}, {%0,%1,%2,%3};"
        : "+f"(d[0]), "+f"(d[1]), "+f"(d[2]), "+f"(d[3])
        : "r"(a0), "r"(a1), "r"(a2), "r"(a3), "r"(b0), "r"(b1));
}

static __device__ __forceinline__ uint32_t packh(float x, float y) {
    __half2 t = __floats2half2_rn(x, y);
    return *(uint32_t*)&t;
}

// ---------------- conversion kernel (x + 4 weights in one launch) ----------
// blockIdx.y: 0 = x (no scale), 1..4 = Wq/Wk/Wv/Wo (x64 scale)
__global__ void conv_all_kernel(const float* __restrict__ xs,
                                const float* __restrict__ s0,
                                const float* __restrict__ s1,
                                const float* __restrict__ s2,
                                const float* __restrict__ s3,
                                int nx4, int nw4)
{
    int i = blockIdx.x * blockDim.x + threadIdx.x;
    if (blockIdx.y == 0) {
        if (i >= nx4) return;
        float4 v = ((const float4*)xs)[i];
        uint2 o;
        o.x = packh(v.x, v.y);
        o.y = packh(v.z, v.w);
        ((uint2*)g_xh)[i] = o;
        return;
    }
    if (i >= nw4) return;
    const float* src; __half* hi;
    switch (blockIdx.y) {
        case 1:  src = s0; hi = g_wqh; break;
        case 2:  src = s1; hi = g_wkh; break;
        case 3:  src = s2; hi = g_wvh; break;
        default: src = s3; hi = g_woh; break;
    }
    float4 v = ((const float4*)src)[i];
    uint2 oh;
    oh.x = packh(v.x * 64.0f, v.y * 64.0f);
    oh.y = packh(v.z * 64.0f, v.w * 64.0f);
    ((uint2*)hi)[i] = oh;
}

// ---------------------------------------------------------------------------
// HMMA GEMM body (1-pass fp16): unchanged from R13/R14 passing config.
// ---------------------------------------------------------------------------
#define GBK 64
#define NCG (DD / GBK)            // 16
#define RSMEM 144
#define A_T (128 * RSMEM)         // 18432
#define B_T (64 * RSMEM)          // 9216
#define BUF_B (A_T + B_T)         // 27648
#define GEMM_SMEM (2 * BUF_B)     // 55296

static __device__ __forceinline__ void gemm_load_chunk(
    const __half* __restrict__ A, const __half* __restrict__ Bhi,
    int bm, int bn, int k0, uint32_t sa_base, int tid)
{
    const __half* ga = A   + (size_t)bm * DD + k0;
    const __half* gb = Bhi + (size_t)bn * DD + k0;
    #pragma unroll
    for (int u = 0; u < 4; u++) {
        int idx = tid + u * 256;
        int row = idx >> 3, seg = idx & 7;
        CP_ASYNC16(sa_base + row * RSMEM + seg * 16,
                   ga + (size_t)row * DD + seg * 8);
    }
    #pragma unroll
    for (int u = 0; u < 2; u++) {
        int idx = tid + u * 256;
        int row = idx >> 3, seg = idx & 7;
        CP_ASYNC16(sa_base + A_T + row * RSMEM + seg * 16,
                   gb + (size_t)row * DD + seg * 8);
    }
}

static __device__ __forceinline__ void gemm_body(
    const __half* __restrict__ A, const __half* __restrict__ Bhi,
    const float* __restrict__ bias, int mode,
    const float* __restrict__ beta,
    float* __restrict__ C, __half* __restrict__ Oh,
    int bn, int bm, char* smc)
{
    const int tid  = threadIdx.x;
    const int wid  = tid >> 5;
    const int lane = tid & 31;
    const uint32_t sb = s2u(smc);

    const int m0 = (wid >> 1) * 32;
    const int n0 = (wid & 1) * 32;

    gemm_load_chunk(A, Bhi, bm, bn, 0, sb, tid);
    CP_COMMIT();

    float acc[2][4][4];
    #pragma unroll
    for (int mi = 0; mi < 2; mi++)
        #pragma unroll
        for (int ni = 0; ni < 4; ni++)
            #pragma unroll
            for (int f = 0; f < 4; f++) acc[mi][ni][f] = 0.0f;

    for (int c = 0; c < NCG; c++) {
        if (c + 1 < NCG) {
            gemm_load_chunk(A, Bhi, bm, bn, (c + 1) * GBK,
                            sb + ((c + 1) & 1) * BUF_B, tid);
            CP_COMMIT();
            CP_WAIT(1);
        } else {
            CP_WAIT(0);
        }
        __syncthreads();

        const uint32_t bufo = (c & 1) * BUF_B;
        const uint32_t AT  = sb + bufo;
        const uint32_t BhT = AT + A_T;

        #pragma unroll
        for (int s = 0; s < 4; s++) {
            const uint32_t kb = s * 32;
            uint32_t bh[4][2], ah[2][4];
            {
                int g = lane >> 3;
                int ntl = g >> 1, half = g & 1;
                uint32_t boff = (uint32_t)(n0 + ntl * 8 + (lane & 7)) * RSMEM
                              + kb + half * 16;
                ldsm_x4(BhT + boff,              bh[0][0], bh[0][1], bh[1][0], bh[1][1]);
                ldsm_x4(BhT + boff + 16 * RSMEM, bh[2][0], bh[2][1], bh[3][0], bh[3][1]);
            }
            #pragma unroll
            for (int mi = 0; mi < 2; mi++) {
                uint32_t aoff = (uint32_t)(m0 + mi * 16 + (lane & 15)) * RSMEM
                              + kb + (lane >> 4) * 16;
                ldsm_x4(AT + aoff, ah[mi][0], ah[mi][1], ah[mi][2], ah[mi][3]);
            }
            #pragma unroll
            for (int mi = 0; mi < 2; mi++)
                #pragma unroll
                for (int ni = 0; ni < 4; ni++)
                    mma16816(acc[mi][ni], ah[mi][0], ah[mi][1], ah[mi][2], ah[mi][3],
                             bh[ni][0], bh[ni][1]);
        }
        __syncthreads();
    }

    const float DS = 1.0f / 64.0f;
    const int erow = lane >> 2;
    const int ecol = (lane & 3) * 2;
    #pragma unroll
    for (int mi = 0; mi < 2; mi++) {
        #pragma unroll
        for (int ni = 0; ni < 4; ni++) {
            int gr = bm + m0 + mi * 16 + erow;
            int gc = bn + n0 + ni * 8 + ecol;
            float v0x = acc[mi][ni][0] * DS + bias[gc];
            float v0y = acc[mi][ni][1] * DS + bias[gc + 1];
            float v1x = acc[mi][ni][2] * DS + bias[gc];
            float v1y = acc[mi][ni][3] * DS + bias[gc + 1];
            if (mode == 0) {
                float2 a = {v0x, v0y}, bb2 = {v1x, v1y};
                *(float2*)(C + (size_t)gr * DD + gc)       = a;
                *(float2*)(C + (size_t)(gr + 8) * DD + gc) = bb2;
            } else {
                int hh = gc >> 6, dh = gc & 63;
                int s0 = gr >> 2, bbi = gr & 3;
                if (mode == 1 || mode == 3) {
                    if (mode == 1) {
                        float f = 2.0f * __expf(-beta[hh]);
                        v0x *= f; v0y *= f; v1x *= f; v1y *= f;
                    }
                    size_t off0 = (((size_t)bbi * HH + hh) * SEQ + s0) * DH + dh;
                    size_t off1 = off0 + 2 * DH;
                    *(uint32_t*)(Oh + off0) = packh(v0x, v0y);
                    *(uint32_t*)(Oh + off1) = packh(v1x, v1y);
                } else {
                    size_t off = (((size_t)bbi * HH + hh) * DH + dh) * SEQ + s0;
                    Oh[off]           = __float2half_rn(v0x);
                    Oh[off + SEQ]     = __float2half_rn(v0y);
                    Oh[off + 2]       = __float2half_rn(v1x);
                    Oh[off + SEQ + 2] = __float2half_rn(v1y);
                }
            }
        }
    }
}

__global__ __launch_bounds__(256, 3)
void gemm_qkv_kernel(const float* __restrict__ beta,
                     const float* __restrict__ bq,
                     const float* __restrict__ bk,
                     const float* __restrict__ bv)
{
    extern __shared__ char smc[];
    const int bn = blockIdx.x * 64;
    const int bm = blockIdx.y * 128;
    if (blockIdx.z == 0)
        gemm_body(g_xh, g_wqh, bq, 1, beta, nullptr, g_qh, bn, bm, smc);
    else if (blockIdx.z == 1)
        gemm_body(g_xh, g_wkh, bk, 3, nullptr, nullptr, g_kh, bn, bm, smc);
    else
        gemm_body(g_xh, g_wvh, bv, 2, nullptr, nullptr, g_vh, bn, bm, smc);
}

__global__ __launch_bounds__(256, 3)
void gemm_out_kernel(const float* __restrict__ bo, float* __restrict__ out)
{
    extern __shared__ char smc[];
    const int bn = blockIdx.x * 64;
    const int bm = blockIdx.y * 128;
    gemm_body(g_ah, g_woh, bo, 0, nullptr, out, nullptr, bn, bm, smc);
}

// ---------------------------------------------------------------------------
// Flash attention — EXACT R14 passing configuration:
// 64-row Q tiles, 128 thr / 4 warps, regs ~162, 3 CTAs/SM (RF-feasible).
// Sink-anchored max-free softmax: p_scaled = exp2(S*C2F + BFOLD).
// ---------------------------------------------------------------------------
#define FRB 144
#define QT_B (64 * FRB)            // 9216
#define STG_B (2 * QT_B)           // 18432
#define FLASH_SMEM (QT_B + 2 * STG_B)   // 46080
#define C2F   0.0901684400556f     // 0.0625 * log2(e)
#define BFOLD (-6.4269504089f)     // 8 - 10*log2(e)
#define LSINK 0.0116223822f        // 256*exp(-10)

static __device__ __forceinline__ void ldsm_b(uint32_t tile, int nbase, int ksb,
                                              int lane, uint32_t* r4)
{
    int g = lane >> 3, ntl = g >> 1, half = g & 1;
    uint32_t addr = tile + (uint32_t)(nbase + ntl * 8 + (lane & 7)) * FRB
                  + ksb + half * 16;
    ldsm_x4(addr, r4[0], r4[1], r4[2], r4[3]);
}

__global__ __launch_bounds__(128, 3)
void flash_mma_kernel(const __half* __restrict__ qh_g,
                      const __half* __restrict__ kh_g,
                      const __half* __restrict__ vh_g,
                      __half* __restrict__ ah_g)
{
    extern __shared__ char smf[];
    const int tid = threadIdx.x, lane = tid & 31, wid = tid >> 5;
    const int qb = (int)gridDim.x - 1 - (int)blockIdx.x;   // LPT order
    const int h = blockIdx.y, b = blockIdx.z;
    const int q0 = qb * 64;
    const uint32_t sb = s2u(smf);
    const uint32_t qhS = sb;

    const size_t bh = (size_t)b * HH + h;
    const char* qhp = (const char*)(qh_g + (bh * SEQ + q0) * DH);
    const __half* khp = kh_g + bh * SEQ * DH;
    const __half* vhp = vh_g + bh * (size_t)DH * SEQ;

    #pragma unroll
    for (int u = 0; u < 4; u++) {
        int lin = tid + u * 128; int row = lin >> 3, seg = lin & 7;
        CP_ASYNC16(qhS + row * FRB + seg * 16, qhp + row * 128 + seg * 16);
    }
    CP_COMMIT();

    {
        uint32_t base = sb + QT_B;
        #pragma unroll
        for (int u = 0; u < 4; u++) {
            int lin = tid + u * 128; int row = lin >> 3, seg = lin & 7;
            CP_ASYNC16(base + row * FRB + seg * 16, khp + (size_t)row * DH + seg * 8);
            CP_ASYNC16(base + QT_B + row * FRB + seg * 16, vhp + (size_t)row * SEQ + seg * 8);
        }
        CP_COMMIT();
    }
    CP_WAIT(0);
    __syncthreads();

    const int qrow0 = wid * 16;
    uint32_t qah[4][4];
    #pragma unroll
    for (int ks = 0; ks < 4; ks++) {
        uint32_t ah = qhS + (uint32_t)(qrow0 + (lane & 15)) * FRB + ks * 32 + (lane >> 4) * 16;
        ldsm_x4(ah, qah[ks][0], qah[ks][1], qah[ks][2], qah[ks][3]);
    }

    float Oa[8][4];
    #pragma unroll
    for (int nt = 0; nt < 8; nt++)
        #pragma unroll
        for (int f = 0; f < 4; f++) Oa[nt][f] = 0.0f;
    float lrow[2] = {LSINK, LSINK};

    for (int jt = 0; jt <= qb; jt++) {
        const int s = jt & 1;
        if (jt < qb) {
            uint32_t base = sb + QT_B + (s ^ 1) * STG_B;
            const int j1 = (jt + 1) * 64;
            #pragma unroll
            for (int u = 0; u < 4; u++) {
                int lin = tid + u * 128; int row = lin >> 3, seg = lin & 7;
                CP_ASYNC16(base + row * FRB + seg * 16,
                           khp + (size_t)(j1 + row) * DH + seg * 8);
                CP_ASYNC16(base + QT_B + row * FRB + seg * 16,
                           vhp + (size_t)row * SEQ + j1 + seg * 8);
            }
            CP_COMMIT();
            CP_WAIT(1);
        } else {
            CP_WAIT(0);
        }
        __syncthreads();

        const uint32_t st = sb + QT_B + s * STG_B;
        const uint32_t khT = st, vhT = st + QT_B;

        // ---- S = Qh Kh^T (raw x16 units) ----
        float S[8][4];
        #pragma unroll
        for (int nt = 0; nt < 8; nt++)
            #pragma unroll
            for (int f = 0; f < 4; f++) S[nt][f] = 0.0f;

        #pragma unroll
        for (int ks = 0; ks < 4; ks++) {
            uint32_t kh4[16];
            #pragma unroll
            for (int p = 0; p < 4; p++)
                ldsm_b(khT, p * 16, ks * 32, lane, kh4 + p * 4);
            #pragma unroll
            for (int nt = 0; nt < 8; nt++)
                mma16816(S[nt], qah[ks][0], qah[ks][1], qah[ks][2], qah[ks][3],
                         kh4[2 * nt], kh4[2 * nt + 1]);
        }

        if (jt == qb) {
            const int j0 = jt * 64;
            #pragma unroll
            for (int nt = 0; nt < 8; nt++) {
                #pragma unroll
                for (int e = 0; e < 4; e++) {
                    int grow = q0 + qrow0 + (lane >> 2) + ((e >= 2) ? 8 : 0);
                    int gcol = j0 + nt * 8 + (lane & 3) * 2 + (e & 1);
                    if (gcol > grow) S[nt][e] = -1e30f;
                }
            }
        }

        // ---- max-free softmax: p_scaled = exp2(S*C2F + BFOLD) ----
        #pragma unroll
        for (int i = 0; i < 2; i++) {
            float rs = 0.0f;
            #pragma unroll
            for (int nt = 0; nt < 8; nt++) {
                float p0 = exp2f(fmaf(S[nt][2 * i],     C2F, BFOLD));
                float p1 = exp2f(fmaf(S[nt][2 * i + 1], C2F, BFOLD));
                S[nt][2 * i] = p0; S[nt][2 * i + 1] = p1;
                rs += p0 + p1;
            }
            rs += __shfl_xor_sync(0xffffffffu, rs, 1);
            rs += __shfl_xor_sync(0xffffffffu, rs, 2);
            lrow[i] += rs;
        }

        // ---- O += P_scaled Vh ----
        #pragma unroll
        for (int ks = 0; ks < 4; ks++) {
            uint32_t ah0 = packh(S[2 * ks][0],     S[2 * ks][1]);
            uint32_t ah1 = packh(S[2 * ks][2],     S[2 * ks][3]);
            uint32_t ah2 = packh(S[2 * ks + 1][0], S[2 * ks + 1][1]);
            uint32_t ah3 = packh(S[2 * ks + 1][2], S[2 * ks + 1][3]);
            uint32_t vh4[16];
            #pragma unroll
            for (int p = 0; p < 4; p++)
                ldsm_b(vhT, p * 16, ks * 32, lane, vh4 + p * 4);
            #pragma unroll
            for (int nt = 0; nt < 8; nt++)
                mma16816(Oa[nt], ah0, ah1, ah2, ah3, vh4[2 * nt], vh4[2 * nt + 1]);
        }
        __syncthreads();
    }

    // ---- epilogue: O = Oa / lrow, store fp16 [s,b,D] ----
    const float inv0 = 1.0f / lrow[0];
    const float inv1 = 1.0f / lrow[1];
    const int r = lane >> 2, c2 = (lane & 3) * 2;
    const int srow0 = q0 + qrow0 + r;
    #pragma unroll
    for (int nt = 0; nt < 8; nt++) {
        int col = h * 64 + nt * 8 + c2;
        float o00 = Oa[nt][0] * inv0, o01 = Oa[nt][1] * inv0;
        float o10 = Oa[nt][2] * inv1, o11 = Oa[nt][3] * inv1;
        size_t off0 = ((size_t)srow0 * BB + b) * DD + col;
        size_t off1 = ((size_t)(srow0 + 8) * BB + b) * DD + col;
        *(uint32_t*)(ah_g + off0) = packh(o00, o01);
        *(uint32_t*)(ah_g + off1) = packh(o10, o11);
    }
}

// ---------------------------------------------------------------------------
extern "C" void kernel_launch(void* const* d_in, const int* in_sizes, int n_in,
                              void* d_out, int out_size)
{
    const float* x    = (const float*)d_in[0];
    const float* beta = (const float*)d_in[2];
    const float* Wq   = (const float*)d_in[3];
    const float* bq   = (const float*)d_in[4];
    const float* Wk   = (const float*)d_in[5];
    const float* bk   = (const float*)d_in[6];
    const float* Wv   = (const float*)d_in[7];
    const float* bv   = (const float*)d_in[8];
    const float* Wo   = (const float*)d_in[9];
    const float* bo   = (const float*)d_in[10];
    float* out = (float*)d_out;

    __half *qh, *kh, *vh, *ah;
    cudaGetSymbolAddress((void**)&qh, g_qh);
    cudaGetSymbolAddress((void**)&kh, g_kh);
    cudaGetSymbolAddress((void**)&vh, g_vh);
    cudaGetSymbolAddress((void**)&ah, g_ah);

    cudaFuncSetAttribute(gemm_qkv_kernel,
                         cudaFuncAttributeMaxDynamicSharedMemorySize, GEMM_SMEM);
    cudaFuncSetAttribute(gemm_out_kernel,
                         cudaFuncAttributeMaxDynamicSharedMemorySize, GEMM_SMEM);
    cudaFuncSetAttribute(flash_mma_kernel,
                         cudaFuncAttributeMaxDynamicSharedMemorySize, FLASH_SMEM);

    const int nx4 = MM * DD / 4;    // 2,097,152
    const int nw4 = DD * DD / 4;    // 262,144

    {
        dim3 cg((nx4 + 255) / 256, 5);   // y=0: x; y=1..4: weights (guarded)
        conv_all_kernel<<<cg, 256>>>(x, Wq, Wk, Wv, Wo, nx4, nw4);
    }

    dim3 qkvgrid(DD / 64, MM / 128, 3);   // (16, 64, 3)
    gemm_qkv_kernel<<<qkvgrid, 256, GEMM_SMEM>>>(beta, bq, bk, bv);

    dim3 fgrid(SEQ / 64, HH, BB);   // (32, 16, 4)
    flash_mma_kernel<<<fgrid, 128, FLASH_SMEM>>>(qh, kh, vh, ah);

    dim3 ogrid(DD / 64, MM / 128);   // (16, 64)
    gemm_out_kernel<<<ogrid, 256, GEMM_SMEM>>>(bo, out);
}

// round 17
// speedup vs baseline: 1.2338x; 1.0547x over previous
#include <cuda_runtime.h>
#include <cuda_fp16.h>
#include <stdint.h>
#include <math.h>

// Problem constants
#define SEQ 2048
#define BB  4
#define DD  1024
#define HH  16
#define DH  64
#define MM  (SEQ*BB)

// ---------------- scratch (device globals; allocation-free) ----------------
__device__ __half g_xh[MM*DD];
__device__ __half g_wqh[DD*DD], g_wkh[DD*DD], g_wvh[DD*DD], g_woh[DD*DD];
__device__ __half g_qh[MM*DD];   // scaled x16 incl beta, [b,h,s,dh]
__device__ __half g_kh[MM*DD];   // [b,h,s,dh]
__device__ __half g_vh[MM*DD];   // transposed [b,h,dh,s]
__device__ __half g_ah[MM*DD];   // att output [s,b,D]

// ---------------- PTX helpers (baseline ISA only) ----------------
static __device__ __forceinline__ uint32_t s2u(const void* p) {
    return (uint32_t)__cvta_generic_to_shared(p);
}

#define CP_ASYNC16(saddr, gptr) \
    asm volatile("cp.async.cg.shared.global [%0], [%1], 16;" :: "r"(saddr), "l"(gptr))
#define CP_COMMIT() asm volatile("cp.async.commit_group;" ::: "memory")
#define CP_WAIT(n)  asm volatile("cp.async.wait_group %0;" :: "n"(n) : "memory")

static __device__ __forceinline__ void ldsm_x4(uint32_t addr,
    uint32_t &r0, uint32_t &r1, uint32_t &r2, uint32_t &r3)
{
    asm volatile("ldmatrix.sync.aligned.m8n8.x4.shared.b16 {%0,%1,%2,%3}, [%4];"
        : "=r"(r0), "=r"(r1), "=r"(r2), "=r"(r3) : "r"(addr));
}

static __device__ __forceinline__ void mma16816(float* d,
    uint32_t a0, uint32_t a1, uint32_t a2, uint32_t a3, uint32_t b0, uint32_t b1)
{
    asm volatile("mma.sync.aligned.m16n8k16.row.col.f32.f16.f16.f32 "
        "{%0,%1,%2,%3}, {%4,%5,%6,%7}, {%8,%9}, {%0,%1,%2,%3};"
        : "+f"(d[0]), "+f"(d[1]), "+f"(d[2]), "+f"(d[3])
        : "r"(a0), "r"(a1), "r"(a2), "r"(a3), "r"(b0), "r"(b1));
}

static __device__ __forceinline__ uint32_t packh(float x, float y) {
    __half2 t = __floats2half2_rn(x, y);
    return *(uint32_t*)&t;
}

// ---------------- conversion kernels (R14 form: right-sized grids) --------
__global__ void convx_kernel(const float* __restrict__ src, int n4)
{
    int i = blockIdx.x * blockDim.x + threadIdx.x;
    if (i >= n4) return;
    float4 v = ((const float4*)src)[i];
    uint2 o;
    o.x = packh(v.x, v.y);
    o.y = packh(v.z, v.w);
    ((uint2*)g_xh)[i] = o;
}

__global__ void split4_kernel(const float* __restrict__ s0, const float* __restrict__ s1,
                              const float* __restrict__ s2, const float* __restrict__ s3,
                              int n4)
{
    int i = blockIdx.x * blockDim.x + threadIdx.x;
    if (i >= n4) return;
    const float* src; __half* hi;
    switch (blockIdx.y) {
        case 0:  src = s0; hi = g_wqh; break;
        case 1:  src = s1; hi = g_wkh; break;
        case 2:  src = s2; hi = g_wvh; break;
        default: src = s3; hi = g_woh; break;
    }
    float4 v = ((const float4*)src)[i];
    uint2 oh;
    oh.x = packh(v.x * 64.0f, v.y * 64.0f);
    oh.y = packh(v.z * 64.0f, v.w * 64.0f);
    ((uint2*)hi)[i] = oh;
}

// ---------------------------------------------------------------------------
// HMMA GEMM body (1-pass fp16), single-sync pipeline:
//   per chunk: wait -> sync -> issue next prefetch -> consume.
// The post-sync prefetch into the other buffer is safe: all warps past the
// sync have finished the previous iteration's consumption (program order).
// ---------------------------------------------------------------------------
#define GBK 64
#define NCG (DD / GBK)            // 16
#define RSMEM 144
#define A_T (128 * RSMEM)         // 18432
#define B_T (64 * RSMEM)          // 9216
#define BUF_B (A_T + B_T)         // 27648
#define GEMM_SMEM (2 * BUF_B)     // 55296

static __device__ __forceinline__ void gemm_load_chunk(
    const __half* __restrict__ A, const __half* __restrict__ Bhi,
    int bm, int bn, int k0, uint32_t sa_base, int tid)
{
    const __half* ga = A   + (size_t)bm * DD + k0;
    const __half* gb = Bhi + (size_t)bn * DD + k0;
    #pragma unroll
    for (int u = 0; u < 4; u++) {
        int idx = tid + u * 256;
        int row = idx >> 3, seg = idx & 7;
        CP_ASYNC16(sa_base + row * RSMEM + seg * 16,
                   ga + (size_t)row * DD + seg * 8);
    }
    #pragma unroll
    for (int u = 0; u < 2; u++) {
        int idx = tid + u * 256;
        int row = idx >> 3, seg = idx & 7;
        CP_ASYNC16(sa_base + A_T + row * RSMEM + seg * 16,
                   gb + (size_t)row * DD + seg * 8);
    }
}

static __device__ __forceinline__ void gemm_body(
    const __half* __restrict__ A, const __half* __restrict__ Bhi,
    const float* __restrict__ bias, int mode,
    const float* __restrict__ beta,
    float* __restrict__ C, __half* __restrict__ Oh,
    int bn, int bm, char* smc)
{
    const int tid  = threadIdx.x;
    const int wid  = tid >> 5;
    const int lane = tid & 31;
    const uint32_t sb = s2u(smc);

    const int m0 = (wid >> 1) * 32;
    const int n0 = (wid & 1) * 32;

    gemm_load_chunk(A, Bhi, bm, bn, 0, sb, tid);
    CP_COMMIT();

    float acc[2][4][4];
    #pragma unroll
    for (int mi = 0; mi < 2; mi++)
        #pragma unroll
        for (int ni = 0; ni < 4; ni++)
            #pragma unroll
            for (int f = 0; f < 4; f++) acc[mi][ni][f] = 0.0f;

    for (int c = 0; c < NCG; c++) {
        CP_WAIT(0);            // chunk c resident (only pending group)
        __syncthreads();       // visible to all; prev consumption done
        if (c + 1 < NCG) {     // prefetch into the buffer freed at iter c-1
            gemm_load_chunk(A, Bhi, bm, bn, (c + 1) * GBK,
                            sb + ((c + 1) & 1) * BUF_B, tid);
            CP_COMMIT();
        }

        const uint32_t bufo = (c & 1) * BUF_B;
        const uint32_t AT  = sb + bufo;
        const uint32_t BhT = AT + A_T;

        #pragma unroll
        for (int s = 0; s < 4; s++) {
            const uint32_t kb = s * 32;
            uint32_t bh[4][2], ah[2][4];
            {
                int g = lane >> 3;
                int ntl = g >> 1, half = g & 1;
                uint32_t boff = (uint32_t)(n0 + ntl * 8 + (lane & 7)) * RSMEM
                              + kb + half * 16;
                ldsm_x4(BhT + boff,              bh[0][0], bh[0][1], bh[1][0], bh[1][1]);
                ldsm_x4(BhT + boff + 16 * RSMEM, bh[2][0], bh[2][1], bh[3][0], bh[3][1]);
            }
            #pragma unroll
            for (int mi = 0; mi < 2; mi++) {
                uint32_t aoff = (uint32_t)(m0 + mi * 16 + (lane & 15)) * RSMEM
                              + kb + (lane >> 4) * 16;
                ldsm_x4(AT + aoff, ah[mi][0], ah[mi][1], ah[mi][2], ah[mi][3]);
            }
            #pragma unroll
            for (int mi = 0; mi < 2; mi++)
                #pragma unroll
                for (int ni = 0; ni < 4; ni++)
                    mma16816(acc[mi][ni], ah[mi][0], ah[mi][1], ah[mi][2], ah[mi][3],
                             bh[ni][0], bh[ni][1]);
        }
        // no trailing sync (hazard covered by next iteration's post-wait sync)
    }

    const float DS = 1.0f / 64.0f;
    const int erow = lane >> 2;
    const int ecol = (lane & 3) * 2;
    #pragma unroll
    for (int mi = 0; mi < 2; mi++) {
        #pragma unroll
        for (int ni = 0; ni < 4; ni++) {
            int gr = bm + m0 + mi * 16 + erow;
            int gc = bn + n0 + ni * 8 + ecol;
            float v0x = acc[mi][ni][0] * DS + bias[gc];
            float v0y = acc[mi][ni][1] * DS + bias[gc + 1];
            float v1x = acc[mi][ni][2] * DS + bias[gc];
            float v1y = acc[mi][ni][3] * DS + bias[gc + 1];
            if (mode == 0) {
                float2 a = {v0x, v0y}, bb2 = {v1x, v1y};
                *(float2*)(C + (size_t)gr * DD + gc)       = a;
                *(float2*)(C + (size_t)(gr + 8) * DD + gc) = bb2;
            } else {
                int hh = gc >> 6, dh = gc & 63;
                int s0 = gr >> 2, bbi = gr & 3;
                if (mode == 1 || mode == 3) {
                    if (mode == 1) {
                        float f = 2.0f * __expf(-beta[hh]);
                        v0x *= f; v0y *= f; v1x *= f; v1y *= f;
                    }
                    size_t off0 = (((size_t)bbi * HH + hh) * SEQ + s0) * DH + dh;
                    size_t off1 = off0 + 2 * DH;
                    *(uint32_t*)(Oh + off0) = packh(v0x, v0y);
                    *(uint32_t*)(Oh + off1) = packh(v1x, v1y);
                } else {
                    size_t off = (((size_t)bbi * HH + hh) * DH + dh) * SEQ + s0;
                    Oh[off]           = __float2half_rn(v0x);
                    Oh[off + SEQ]     = __float2half_rn(v0y);
                    Oh[off + 2]       = __float2half_rn(v1x);
                    Oh[off + SEQ + 2] = __float2half_rn(v1y);
                }
            }
        }
    }
}

__global__ __launch_bounds__(256, 3)
void gemm_qkv_kernel(const float* __restrict__ beta,
                     const float* __restrict__ bq,
                     const float* __restrict__ bk,
                     const float* __restrict__ bv)
{
    extern __shared__ char smc[];
    const int bn = blockIdx.x * 64;
    const int bm = blockIdx.y * 128;
    if (blockIdx.z == 0)
        gemm_body(g_xh, g_wqh, bq, 1, beta, nullptr, g_qh, bn, bm, smc);
    else if (blockIdx.z == 1)
        gemm_body(g_xh, g_wkh, bk, 3, nullptr, nullptr, g_kh, bn, bm, smc);
    else
        gemm_body(g_xh, g_wvh, bv, 2, nullptr, nullptr, g_vh, bn, bm, smc);
}

__global__ __launch_bounds__(256, 3)
void gemm_out_kernel(const float* __restrict__ bo, float* __restrict__ out)
{
    extern __shared__ char smc[];
    const int bn = blockIdx.x * 64;
    const int bm = blockIdx.y * 128;
    gemm_body(g_ah, g_woh, bo, 0, nullptr, out, nullptr, bn, bm, smc);
}

// ---------------------------------------------------------------------------
// Flash attention — R14 shape (64-row Q, 128 thr, 3 CTAs/SM) with the same
// single-sync pipeline restructure. Sink-anchored max-free softmax.
// ---------------------------------------------------------------------------
#define FRB 144
#define QT_B (64 * FRB)            // 9216
#define STG_B (2 * QT_B)           // 18432
#define FLASH_SMEM (QT_B + 2 * STG_B)   // 46080
#define C2F   0.0901684400556f     // 0.0625 * log2(e)
#define BFOLD (-6.4269504089f)     // 8 - 10*log2(e)
#define LSINK 0.0116223822f        // 256*exp(-10)

static __device__ __forceinline__ void ldsm_b(uint32_t tile, int nbase, int ksb,
                                              int lane, uint32_t* r4)
{
    int g = lane >> 3, ntl = g >> 1, half = g & 1;
    uint32_t addr = tile + (uint32_t)(nbase + ntl * 8 + (lane & 7)) * FRB
                  + ksb + half * 16;
    ldsm_x4(addr, r4[0], r4[1], r4[2], r4[3]);
}

__global__ __launch_bounds__(128, 3)
void flash_mma_kernel(const __half* __restrict__ qh_g,
                      const __half* __restrict__ kh_g,
                      const __half* __restrict__ vh_g,
                      __half* __restrict__ ah_g)
{
    extern __shared__ char smf[];
    const int tid = threadIdx.x, lane = tid & 31, wid = tid >> 5;
    const int qb = (int)gridDim.x - 1 - (int)blockIdx.x;   // LPT order
    const int h = blockIdx.y, b = blockIdx.z;
    const int q0 = qb * 64;
    const uint32_t sb = s2u(smf);
    const uint32_t qhS = sb;

    const size_t bh = (size_t)b * HH + h;
    const char* qhp = (const char*)(qh_g + (bh * SEQ + q0) * DH);
    const __half* khp = kh_g + bh * SEQ * DH;
    const __half* vhp = vh_g + bh * (size_t)DH * SEQ;

    // Q tile + stage 0 prefetch (one group)
    #pragma unroll
    for (int u = 0; u < 4; u++) {
        int lin = tid + u * 128; int row = lin >> 3, seg = lin & 7;
        CP_ASYNC16(qhS + row * FRB + seg * 16, qhp + row * 128 + seg * 16);
    }
    {
        uint32_t base = sb + QT_B;
        #pragma unroll
        for (int u = 0; u < 4; u++) {
            int lin = tid + u * 128; int row = lin >> 3, seg = lin & 7;
            CP_ASYNC16(base + row * FRB + seg * 16, khp + (size_t)row * DH + seg * 8);
            CP_ASYNC16(base + QT_B + row * FRB + seg * 16, vhp + (size_t)row * SEQ + seg * 8);
        }
    }
    CP_COMMIT();

    float Oa[8][4];
    #pragma unroll
    for (int nt = 0; nt < 8; nt++)
        #pragma unroll
        for (int f = 0; f < 4; f++) Oa[nt][f] = 0.0f;
    float lrow[2] = {LSINK, LSINK};

    const int qrow0 = wid * 16;
    uint32_t qah[4][4];
    bool qloaded = false;

    for (int jt = 0; jt <= qb; jt++) {
        const int s = jt & 1;
        CP_WAIT(0);            // stage jt (and Q, first iter) resident
        __syncthreads();
        if (jt < qb) {         // prefetch into buffer freed at iter jt-1
            uint32_t base = sb + QT_B + (s ^ 1) * STG_B;
            const int j1 = (jt + 1) * 64;
            #pragma unroll
            for (int u = 0; u < 4; u++) {
                int lin = tid + u * 128; int row = lin >> 3, seg = lin & 7;
                CP_ASYNC16(base + row * FRB + seg * 16,
                           khp + (size_t)(j1 + row) * DH + seg * 8);
                CP_ASYNC16(base + QT_B + row * FRB + seg * 16,
                           vhp + (size_t)row * SEQ + j1 + seg * 8);
            }
            CP_COMMIT();
        }
        if (!qloaded) {        // Q fragments (once, after first sync)
            #pragma unroll
            for (int ks = 0; ks < 4; ks++) {
                uint32_t ah = qhS + (uint32_t)(qrow0 + (lane & 15)) * FRB
                            + ks * 32 + (lane >> 4) * 16;
                ldsm_x4(ah, qah[ks][0], qah[ks][1], qah[ks][2], qah[ks][3]);
            }
            qloaded = true;
        }

        const uint32_t st = sb + QT_B + s * STG_B;
        const uint32_t khT = st, vhT = st + QT_B;

        // ---- S = Qh Kh^T (raw x16 units) ----
        float S[8][4];
        #pragma unroll
        for (int nt = 0; nt < 8; nt++)
            #pragma unroll
            for (int f = 0; f < 4; f++) S[nt][f] = 0.0f;

        #pragma unroll
        for (int ks = 0; ks < 4; ks++) {
            uint32_t kh4[16];
            #pragma unroll
            for (int p = 0; p < 4; p++)
                ldsm_b(khT, p * 16, ks * 32, lane, kh4 + p * 4);
            #pragma unroll
            for (int nt = 0; nt < 8; nt++)
                mma16816(S[nt], qah[ks][0], qah[ks][1], qah[ks][2], qah[ks][3],
                         kh4[2 * nt], kh4[2 * nt + 1]);
        }

        if (jt == qb) {
            const int j0 = jt * 64;
            #pragma unroll
            for (int nt = 0; nt < 8; nt++) {
                #pragma unroll
                for (int e = 0; e < 4; e++) {
                    int grow = q0 + qrow0 + (lane >> 2) + ((e >= 2) ? 8 : 0);
                    int gcol = j0 + nt * 8 + (lane & 3) * 2 + (e & 1);
                    if (gcol > grow) S[nt][e] = -1e30f;
                }
            }
        }

        // ---- max-free softmax: p_scaled = exp2(S*C2F + BFOLD) ----
        #pragma unroll
        for (int i = 0; i < 2; i++) {
            float rs = 0.0f;
            #pragma unroll
            for (int nt = 0; nt < 8; nt++) {
                float p0 = exp2f(fmaf(S[nt][2 * i],     C2F, BFOLD));
                float p1 = exp2f(fmaf(S[nt][2 * i + 1], C2F, BFOLD));
                S[nt][2 * i] = p0; S[nt][2 * i + 1] = p1;
                rs += p0 + p1;
            }
            rs += __shfl_xor_sync(0xffffffffu, rs, 1);
            rs += __shfl_xor_sync(0xffffffffu, rs, 2);
            lrow[i] += rs;
        }

        // ---- O += P_scaled Vh ----
        #pragma unroll
        for (int ks = 0; ks < 4; ks++) {
            uint32_t ah0 = packh(S[2 * ks][0],     S[2 * ks][1]);
            uint32_t ah1 = packh(S[2 * ks][2],     S[2 * ks][3]);
            uint32_t ah2 = packh(S[2 * ks + 1][0], S[2 * ks + 1][1]);
            uint32_t ah3 = packh(S[2 * ks + 1][2], S[2 * ks + 1][3]);
            uint32_t vh4[16];
            #pragma unroll
            for (int p = 0; p < 4; p++)
                ldsm_b(vhT, p * 16, ks * 32, lane, vh4 + p * 4);
            #pragma unroll
            for (int nt = 0; nt < 8; nt++)
                mma16816(Oa[nt], ah0, ah1, ah2, ah3, vh4[2 * nt], vh4[2 * nt + 1]);
        }
        // no trailing sync (covered by next iteration's post-wait sync)
    }

    // ---- epilogue: O = Oa / lrow, store fp16 [s,b,D] ----
    const float inv0 = 1.0f / lrow[0];
    const float inv1 = 1.0f / lrow[1];
    const int r = lane >> 2, c2 = (lane & 3) * 2;
    const int srow0 = q0 + qrow0 + r;
    #pragma unroll
    for (int nt = 0; nt < 8; nt++) {
        int col = h * 64 + nt * 8 + c2;
        float o00 = Oa[nt][0] * inv0, o01 = Oa[nt][1] * inv0;
        float o10 = Oa[nt][2] * inv1, o11 = Oa[nt][3] * inv1;
        size_t off0 = ((size_t)srow0 * BB + b) * DD + col;
        size_t off1 = ((size_t)(srow0 + 8) * BB + b) * DD + col;
        *(uint32_t*)(ah_g + off0) = packh(o00, o01);
        *(uint32_t*)(ah_g + off1) = packh(o10, o11);
    }
}

// ---------------------------------------------------------------------------
extern "C" void kernel_launch(void* const* d_in, const int* in_sizes, int n_in,
                              void* d_out, int out_size)
{
    const float* x    = (const float*)d_in[0];
    const float* beta = (const float*)d_in[2];
    const float* Wq   = (const float*)d_in[3];
    const float* bq   = (const float*)d_in[4];
    const float* Wk   = (const float*)d_in[5];
    const float* bk   = (const float*)d_in[6];
    const float* Wv   = (const float*)d_in[7];
    const float* bv   = (const float*)d_in[8];
    const float* Wo   = (const float*)d_in[9];
    const float* bo   = (const float*)d_in[10];
    float* out = (float*)d_out;

    __half *qh, *kh, *vh, *ah;
    cudaGetSymbolAddress((void**)&qh, g_qh);
    cudaGetSymbolAddress((void**)&kh, g_kh);
    cudaGetSymbolAddress((void**)&vh, g_vh);
    cudaGetSymbolAddress((void**)&ah, g_ah);

    cudaFuncSetAttribute(gemm_qkv_kernel,
                         cudaFuncAttributeMaxDynamicSharedMemorySize, GEMM_SMEM);
    cudaFuncSetAttribute(gemm_out_kernel,
                         cudaFuncAttributeMaxDynamicSharedMemorySize, GEMM_SMEM);
    cudaFuncSetAttribute(flash_mma_kernel,
                         cudaFuncAttributeMaxDynamicSharedMemorySize, FLASH_SMEM);

    const int nx4 = MM * DD / 4;    // 2,097,152
    const int nw4 = DD * DD / 4;    // 262,144

    convx_kernel<<<(nx4 + 255) / 256, 256>>>(x, nx4);
    {
        dim3 sg((nw4 + 255) / 256, 4);
        split4_kernel<<<sg, 256>>>(Wq, Wk, Wv, Wo, nw4);
    }

    dim3 qkvgrid(DD / 64, MM / 128, 3);   // (16, 64, 3)
    gemm_qkv_kernel<<<qkvgrid, 256, GEMM_SMEM>>>(beta, bq, bk, bv);

    dim3 fgrid(SEQ / 64, HH, BB);   // (32, 16, 4)
    flash_mma_kernel<<<fgrid, 128, FLASH_SMEM>>>(qh, kh, vh, ah);

    dim3 ogrid(DD / 64, MM / 128);   // (16, 64)
    gemm_out_kernel<<<ogrid, 256, GEMM_SMEM>>>(bo, out);
}